// round 7
// baseline (speedup 1.0000x reference)
#include <cuda_runtime.h>
#include <cuda_bf16.h>
#include <math_constants.h>
#include <cstdint>

// ---------------- Problem constants ----------------
#define B_    16
#define S_    20
#define SP    32
#define T_    1280
#define H_    768
#define NI    50000
#define NP    50048            // N padded to multiple of 128
#define MP    (B_ * SP)        // 512 padded M rows (b-major, 32 per b)
#define TEMP_ 0.05f
#define EPS_  1e-8f

// ---------------- GEMM config ----------------
#define BM 128
#define BN 128
#define BK 64
#define NSTAGE 3
#define NKCH (H_ / BK)          // 12
#define TILE_B   16384          // one 128x64 bf16 tile (128 rows x 128B)
#define STAGE_B  (4 * TILE_B)   // Ahi, Alo, Ehi, Elo
#define DSMEM_BYTES (NSTAGE * STAGE_B + 1024)   // 197632

// ---------------- Scratch (device globals) ----------------
__device__ __nv_bfloat16 g_Ahi[(size_t)MP * H_];
__device__ __nv_bfloat16 g_Alo[(size_t)MP * H_];
__device__ __nv_bfloat16 g_Ehi[(size_t)NP * H_];   // prescaled by 1/||e||
__device__ __nv_bfloat16 g_Elo[(size_t)NP * H_];
__device__ float         g_valid[MP];

// ---------------- helpers ----------------
static __device__ __forceinline__ uint32_t smem_u32(const void* p) {
    uint32_t a;
    asm("{ .reg .u64 t; cvta.to.shared.u64 t, %1; cvt.u32.u64 %0, t; }" : "=r"(a) : "l"(p));
    return a;
}
static __device__ __forceinline__ uint32_t sw128(uint32_t o) { return o ^ ((o >> 3) & 0x70); }

static __device__ __forceinline__ void cp16(uint32_t dst, const void* src) {
    asm volatile("cp.async.cg.shared.global [%0], [%1], 16;" :: "r"(dst), "l"(src));
}
#define CP_COMMIT()   asm volatile("cp.async.commit_group;" ::: "memory")
#define CP_WAIT(n)    asm volatile("cp.async.wait_group %0;" :: "n"(n) : "memory")

static __device__ __forceinline__ void ldsm_x4(uint32_t* r, uint32_t addr) {
    asm volatile("ldmatrix.sync.aligned.m8n8.x4.shared.b16 {%0,%1,%2,%3}, [%4];"
        : "=r"(r[0]), "=r"(r[1]), "=r"(r[2]), "=r"(r[3]) : "r"(addr));
}
static __device__ __forceinline__ void mma16816(float* d, const uint32_t* a, const uint32_t* b) {
    asm volatile("mma.sync.aligned.m16n8k16.row.col.f32.bf16.bf16.f32 "
        "{%0,%1,%2,%3}, {%4,%5,%6,%7}, {%8,%9}, {%0,%1,%2,%3};"
        : "+f"(d[0]), "+f"(d[1]), "+f"(d[2]), "+f"(d[3])
        : "r"(a[0]), "r"(a[1]), "r"(a[2]), "r"(a[3]), "r"(b[0]), "r"(b[1]));
}
static __device__ __forceinline__ unsigned f2o(float x) {
    unsigned u = __float_as_uint(x);
    return (u >> 31) ? ~u : (u | 0x80000000u);
}
static __device__ __forceinline__ float o2f(unsigned u) {
    return (u >> 31) ? __uint_as_float(u & 0x7fffffffu) : __uint_as_float(~u);
}

// ---------------------------------------------------------------------------
// Kernel 1: pooling -> bf16 hi/lo A + validity. grid=512 blocks, 256 threads.
// Item s's tokens occupy the contiguous range [s*64, s*64+64) (or none).
// ---------------------------------------------------------------------------
__global__ void pool_kernel(const float* __restrict__ hidden,
                            const int*   __restrict__ pos) {
    const int blk = blockIdx.x;
    const int b = blk >> 5, s = blk & 31;
    const int tid = threadIdx.x;

    uint32_t* ahr = (uint32_t*)&g_Ahi[(size_t)blk * H_];
    uint32_t* alr = (uint32_t*)&g_Alo[(size_t)blk * H_];

    __shared__ int   spos[64];
    __shared__ float red[8];

    int cnt = 0;
    if (s < S_) {
        if (tid < 64) spos[tid] = pos[b * T_ + s * 64 + tid];
        __syncthreads();
        const int target = s + 1;
        #pragma unroll 8
        for (int t = 0; t < 64; t++) cnt += (spos[t] == target);
    }

    if (cnt == 0) {
        #pragma unroll
        for (int k = 0; k < 2; k++) {
            int i = tid + k * 256;
            if (i < H_ / 2) { ahr[i] = 0u; alr[i] = 0u; }
        }
        if (tid == 0) g_valid[blk] = 0.f;
        return;
    }

    const int target = s + 1;
    const float* hb = hidden + ((size_t)b * T_ + (size_t)s * 64) * H_;
    float a0 = 0.f, a1 = 0.f, a2 = 0.f;
    #pragma unroll 8
    for (int t = 0; t < 64; t++) {
        float m = (spos[t] == target) ? 1.f : 0.f;
        const float* r = hb + (size_t)t * H_;
        a0 += m * r[tid];
        a1 += m * r[tid + 256];
        a2 += m * r[tid + 512];
    }
    const float inv_c = 1.f / (float)cnt;
    a0 *= inv_c; a1 *= inv_c; a2 *= inv_c;

    float ss = a0 * a0 + a1 * a1 + a2 * a2;
    #pragma unroll
    for (int o = 16; o; o >>= 1) ss += __shfl_down_sync(0xffffffffu, ss, o);
    if ((tid & 31) == 0) red[tid >> 5] = ss;
    __syncthreads();
    if (tid < 8) {
        float v = red[tid];
        #pragma unroll
        for (int o = 4; o; o >>= 1) v += __shfl_down_sync(0xffu, v, o);
        if (tid == 0) red[0] = v;
    }
    __syncthreads();

    const float scale = 1.f / (fmaxf(sqrtf(red[0]), EPS_) * TEMP_);

    float vals[3] = { a0 * scale, a1 * scale, a2 * scale };
    #pragma unroll
    for (int k = 0; k < 3; k++) {
        int c = tid + k * 256;
        float x = vals[k];
        __nv_bfloat16 h = __float2bfloat16_rn(x);
        __nv_bfloat16 l = __float2bfloat16_rn(x - __bfloat162float(h));
        g_Ahi[(size_t)blk * H_ + c] = h;
        g_Alo[(size_t)blk * H_ + c] = l;
    }
    if (tid == 0) g_valid[blk] = 1.f;
}

// ---------------------------------------------------------------------------
// Kernel 2: E fp32 -> normalize-prescale -> bf16 hi/lo. One warp per row.
// ---------------------------------------------------------------------------
__global__ __launch_bounds__(256)
void eprep_kernel(const float* __restrict__ emb) {
    const int n = blockIdx.x * 8 + (threadIdx.x >> 5);
    const int lane = threadIdx.x & 31;
    if (n >= NP) return;

    uint2* hrow = (uint2*)&g_Ehi[(size_t)n * H_];
    uint2* lrow = (uint2*)&g_Elo[(size_t)n * H_];

    if (n >= NI) {
        #pragma unroll
        for (int u = 0; u < 6; u++) {
            int i = u * 32 + lane;
            hrow[i] = make_uint2(0u, 0u);
            lrow[i] = make_uint2(0u, 0u);
        }
        return;
    }

    const float4* erow = (const float4*)&emb[(size_t)n * H_];
    float4 x[6];
    float ssq = 0.f;
    #pragma unroll
    for (int u = 0; u < 6; u++) {
        x[u] = erow[u * 32 + lane];
        ssq += x[u].x * x[u].x + x[u].y * x[u].y + x[u].z * x[u].z + x[u].w * x[u].w;
    }
    #pragma unroll
    for (int o = 16; o; o >>= 1) ssq += __shfl_xor_sync(0xffffffffu, ssq, o);
    const float invn = 1.f / fmaxf(sqrtf(ssq), EPS_);

    #pragma unroll
    for (int u = 0; u < 6; u++) {
        int i = u * 32 + lane;
        float v0 = x[u].x * invn, v1 = x[u].y * invn;
        float v2 = x[u].z * invn, v3 = x[u].w * invn;
        __nv_bfloat16 h0 = __float2bfloat16_rn(v0);
        __nv_bfloat16 h1 = __float2bfloat16_rn(v1);
        __nv_bfloat16 h2 = __float2bfloat16_rn(v2);
        __nv_bfloat16 h3 = __float2bfloat16_rn(v3);
        __nv_bfloat16 l0 = __float2bfloat16_rn(v0 - __bfloat162float(h0));
        __nv_bfloat16 l1 = __float2bfloat16_rn(v1 - __bfloat162float(h1));
        __nv_bfloat16 l2 = __float2bfloat16_rn(v2 - __bfloat162float(h2));
        __nv_bfloat16 l3 = __float2bfloat16_rn(v3 - __bfloat162float(h3));
        __nv_bfloat162 hp0(h0, h1), hp1(h2, h3), lp0(l0, l1), lp1(l2, l3);
        hrow[i] = make_uint2(*(uint32_t*)&hp0, *(uint32_t*)&hp1);
        lrow[i] = make_uint2(*(uint32_t*)&lp0, *(uint32_t*)&lp1);
    }
}

// ---------------------------------------------------------------------------
// Kernel 3: bf16 mma.sync GEMM + fused maxsim epilogue.
// grid = (MP/128, NP/128)  [m FAST -> 4 consumers of each E n-block adjacent],
// 256 threads (8 warps, 2x4 of m64n32 warp tiles), 3-stage cp.async pipeline.
// ---------------------------------------------------------------------------
__global__ __launch_bounds__(256, 1)
void gemm_mma(float* __restrict__ out) {
    extern __shared__ __align__(16) char dsm[];
    __shared__ unsigned s_red[4][BN];
    __shared__ float s_val[BM];

    const int tid  = threadIdx.x;
    const int wid  = tid >> 5;
    const int lane = tid & 31;
    const int wm   = wid >> 2;        // 0..1  (m64 tile)
    const int wn   = wid & 3;         // 0..3  (n32 tile)
    const int m0   = blockIdx.x * BM;
    const int n0   = blockIdx.y * BN;

    const uint32_t base = (smem_u32(dsm) + 1023u) & ~1023u;
    const unsigned NEG = f2o(-CUDART_INF_F);

    if (tid < BM) s_val[tid] = g_valid[m0 + tid];
    #pragma unroll
    for (int k = 0; k < 2; k++) {
        int i = tid + k * 256;
        s_red[i >> 7][i & 127] = NEG;
    }

    // ---- stage loads: 4 tiles of 1024 16B-chunks each ----
    auto issue_loads = [&](int kc, int stg) {
        const uint32_t sb = base + stg * STAGE_B;
        const __nv_bfloat16* srcs[4] = {
            g_Ahi + (size_t)m0 * H_, g_Alo + (size_t)m0 * H_,
            g_Ehi + (size_t)n0 * H_, g_Elo + (size_t)n0 * H_ };
        #pragma unroll
        for (int t = 0; t < 4; t++) {
            const uint32_t tb = sb + t * TILE_B;
            const __nv_bfloat16* src = srcs[t];
            #pragma unroll
            for (int j = 0; j < 4; j++) {
                int i = tid + j * 256;        // 0..1023
                int row = i >> 3, u = i & 7;
                cp16(tb + sw128((uint32_t)(row * 128 + u * 16)),
                     src + (size_t)row * H_ + kc * BK + u * 8);
            }
        }
        CP_COMMIT();
    };

    float acc[4][4][4];
    #pragma unroll
    for (int mi = 0; mi < 4; mi++)
        #pragma unroll
        for (int ni = 0; ni < 4; ni++)
            #pragma unroll
            for (int q = 0; q < 4; q++) acc[mi][ni][q] = 0.f;

    // per-lane ldmatrix row offsets (bytes), within a tile
    const uint32_t a_row = (uint32_t)(wm * 64 + ((lane >> 3) & 1) * 8 + (lane & 7)) * 128;
    const uint32_t a_u   = (uint32_t)((lane >> 4) & 1) * 16;
    const uint32_t b_row = (uint32_t)(wn * 32 + ((lane >> 4) & 1) * 8 + (lane & 7)) * 128;
    const uint32_t b_u   = (uint32_t)((lane >> 3) & 1) * 16;

    issue_loads(0, 0);
    issue_loads(1, 1);

    for (int kc = 0; kc < NKCH; kc++) {
        CP_WAIT(1);                 // stage kc's data resident (own thread)
        __syncthreads();            // ... and everyone else's
        if (kc + 2 < NKCH) issue_loads(kc + 2, (kc + 2) % NSTAGE);

        const uint32_t sb  = base + (kc % NSTAGE) * STAGE_B;
        const uint32_t Ahs = sb;
        const uint32_t Als = sb + TILE_B;
        const uint32_t Ehs = sb + 2 * TILE_B;
        const uint32_t Els = sb + 3 * TILE_B;

        #pragma unroll
        for (int s = 0; s < 4; s++) {
            const uint32_t ku = (uint32_t)(s * 32);
            uint32_t ah[4][4], al[4][4], bh[2][4], bl[2][4];
            #pragma unroll
            for (int mi = 0; mi < 4; mi++) {
                uint32_t off = sw128(a_row + (uint32_t)(mi * 16 * 128) + ku + a_u);
                ldsm_x4(ah[mi], Ahs + off);
                ldsm_x4(al[mi], Als + off);
            }
            #pragma unroll
            for (int nj = 0; nj < 2; nj++) {
                uint32_t off = sw128(b_row + (uint32_t)(nj * 16 * 128) + ku + b_u);
                ldsm_x4(bh[nj], Ehs + off);
                ldsm_x4(bl[nj], Els + off);
            }
            #pragma unroll
            for (int mi = 0; mi < 4; mi++)
                #pragma unroll
                for (int ni = 0; ni < 4; ni++) {
                    mma16816(acc[mi][ni], ah[mi], &bh[ni >> 1][(ni & 1) * 2]);
                    mma16816(acc[mi][ni], al[mi], &bh[ni >> 1][(ni & 1) * 2]);
                    mma16816(acc[mi][ni], ah[mi], &bl[ni >> 1][(ni & 1) * 2]);
                }
        }
    }

    // ---- epilogue: mask, 32-row session max via smem ordered atomicMax ----
    #pragma unroll
    for (int mi = 0; mi < 4; mi++) {
        const int r0 = wm * 64 + mi * 16 + (lane >> 2);
        const bool ok0 = s_val[r0]     > 0.5f;
        const bool ok1 = s_val[r0 + 8] > 0.5f;
        const int g = wm * 2 + (mi >> 1);
        #pragma unroll
        for (int ni = 0; ni < 4; ni++) {
            const int c = wn * 32 + ni * 8 + (lane & 3) * 2;
            unsigned u0 = ok0 ? f2o(acc[mi][ni][0]) : NEG;
            unsigned u1 = ok0 ? f2o(acc[mi][ni][1]) : NEG;
            unsigned u2 = ok1 ? f2o(acc[mi][ni][2]) : NEG;
            unsigned u3 = ok1 ? f2o(acc[mi][ni][3]) : NEG;
            unsigned m0v = u0 > u2 ? u0 : u2;
            unsigned m1v = u1 > u3 ? u1 : u3;
            atomicMax(&s_red[g][c], m0v);
            atomicMax(&s_red[g][c + 1], m1v);
        }
    }
    __syncthreads();

    #pragma unroll
    for (int k = 0; k < 2; k++) {
        int i = tid + k * 256;             // 0..511
        int g = i >> 7, c = i & 127;
        int n = n0 + c;
        if (n < NI) {
            int b = blockIdx.x * 4 + g;
            out[(size_t)b * NI + n] = o2f(s_red[g][c]);
        }
    }
}

// ---------------------------------------------------------------------------
// Launch
// ---------------------------------------------------------------------------
extern "C" void kernel_launch(void* const* d_in, const int* in_sizes, int n_in,
                              void* d_out, int out_size) {
    const float* hidden = (const float*)d_in[0];   // [16,1280,768] f32
    const float* emb    = (const float*)d_in[1];   // [50000,768] f32
    const int*   pos    = (const int*)  d_in[3];   // [16,1280] i32
    float* out = (float*)d_out;                    // [16,50000] f32

    cudaFuncSetAttribute(gemm_mma, cudaFuncAttributeMaxDynamicSharedMemorySize, DSMEM_BYTES);

    pool_kernel<<<MP, 256>>>(hidden, pos);
    eprep_kernel<<<NP / 8, 256>>>(emb);
    gemm_mma<<<dim3(MP / BM, NP / BN), 256, DSMEM_BYTES>>>(out);
}

// round 10
// speedup vs baseline: 1.2841x; 1.2841x over previous
#include <cuda_runtime.h>
#include <cuda_bf16.h>
#include <math_constants.h>
#include <cstdint>

// ---------------- Problem constants ----------------
#define B_    16
#define S_    20
#define RPB   24               // rows per batch session group (pad 20 -> 24)
#define T_    1280
#define H_    768
#define NI    50000
#define NP    50048            // N padded to multiple of 128
#define MP    (B_ * RPB)       // 384 padded M rows
#define TEMP_ 0.05f
#define EPS_  1e-8f

// ---------------- GEMM config ----------------
#define BM 128
#define BN 128
#define BK 64
#define NSTAGE 3
#define NKCH (H_ / BK)          // 12
#define TILE_B   16384          // one 128x64 bf16 tile (128 rows x 128B)
#define STAGE_B  (4 * TILE_B)   // Ahi, Alo, Ehi, Elo
#define DSMEM_BYTES (NSTAGE * STAGE_B + 1024)   // 197632

#define NEG_ORD 0x007FFFFFu     // f2o(-inf)

// ---------------- Scratch (device globals) ----------------
__device__ __nv_bfloat16 g_Ahi[(size_t)MP * H_];
__device__ __nv_bfloat16 g_Alo[(size_t)MP * H_];
__device__ __nv_bfloat16 g_Ehi[(size_t)NP * H_];   // prescaled by 1/||e||
__device__ __nv_bfloat16 g_Elo[(size_t)NP * H_];
__device__ float         g_valid[MP];
__device__ unsigned      g_outU[(size_t)B_ * NP];  // ordered-uint maxsim accumulator

// ---------------- helpers ----------------
static __device__ __forceinline__ uint32_t smem_u32(const void* p) {
    uint32_t a;
    asm("{ .reg .u64 t; cvta.to.shared.u64 t, %1; cvt.u32.u64 %0, t; }" : "=r"(a) : "l"(p));
    return a;
}
static __device__ __forceinline__ uint32_t sw128(uint32_t o) { return o ^ ((o >> 3) & 0x70); }

static __device__ __forceinline__ void cp16(uint32_t dst, const void* src) {
    asm volatile("cp.async.cg.shared.global [%0], [%1], 16;" :: "r"(dst), "l"(src));
}
#define CP_COMMIT()   asm volatile("cp.async.commit_group;" ::: "memory")
#define CP_WAIT(n)    asm volatile("cp.async.wait_group %0;" :: "n"(n) : "memory")

static __device__ __forceinline__ void ldsm_x4(uint32_t* r, uint32_t addr) {
    asm volatile("ldmatrix.sync.aligned.m8n8.x4.shared.b16 {%0,%1,%2,%3}, [%4];"
        : "=r"(r[0]), "=r"(r[1]), "=r"(r[2]), "=r"(r[3]) : "r"(addr));
}
static __device__ __forceinline__ void mma16816(float* d, const uint32_t* a, const uint32_t* b) {
    asm volatile("mma.sync.aligned.m16n8k16.row.col.f32.bf16.bf16.f32 "
        "{%0,%1,%2,%3}, {%4,%5,%6,%7}, {%8,%9}, {%0,%1,%2,%3};"
        : "+f"(d[0]), "+f"(d[1]), "+f"(d[2]), "+f"(d[3])
        : "r"(a[0]), "r"(a[1]), "r"(a[2]), "r"(a[3]), "r"(b[0]), "r"(b[1]));
}
static __device__ __forceinline__ unsigned f2o(float x) {
    unsigned u = __float_as_uint(x);
    return (u >> 31) ? ~u : (u | 0x80000000u);
}
static __device__ __forceinline__ float o2f(unsigned u) {
    return (u >> 31) ? __uint_as_float(u & 0x7fffffffu) : __uint_as_float(~u);
}

// ---------------------------------------------------------------------------
// Kernel 1 (fused prep): three block roles.
//   blocks [0, MP)            : pooling -> bf16 hi/lo A + validity
//   blocks [MP, MP + NP/8)    : E fp32 -> normalize -> bf16 hi/lo (8 rows/blk)
//   blocks [MP+NP/8, ...)     : init g_outU to NEG_ORD
// ---------------------------------------------------------------------------
#define EPREP_BLKS (NP / 8)                 // 6256
#define INIT_BLKS  ((B_ * NP + 2047) / 2048) // 392
#define PREP_GRID  (MP + EPREP_BLKS + INIT_BLKS)

__global__ __launch_bounds__(256)
void prep_kernel(const float* __restrict__ hidden,
                 const int*   __restrict__ pos,
                 const float* __restrict__ emb) {
    const int blk = blockIdx.x;
    const int tid = threadIdx.x;

    // ---------------- role 3: output-accumulator init ----------------
    if (blk >= MP + EPREP_BLKS) {
        const int rb = blk - MP - EPREP_BLKS;
        #pragma unroll
        for (int k = 0; k < 8; k++) {
            int idx = rb * 2048 + k * 256 + tid;
            if (idx < B_ * NP) g_outU[idx] = NEG_ORD;
        }
        return;
    }

    // ---------------- role 2: E prep ----------------
    if (blk >= MP) {
        const int n = (blk - MP) * 8 + (tid >> 5);
        const int lane = tid & 31;
        uint2* hrow = (uint2*)&g_Ehi[(size_t)n * H_];
        uint2* lrow = (uint2*)&g_Elo[(size_t)n * H_];
        if (n >= NI) {
            #pragma unroll
            for (int u = 0; u < 6; u++) {
                hrow[u * 32 + lane] = make_uint2(0u, 0u);
                lrow[u * 32 + lane] = make_uint2(0u, 0u);
            }
            return;
        }
        const float4* erow = (const float4*)&emb[(size_t)n * H_];
        float4 x[6];
        float ssq = 0.f;
        #pragma unroll
        for (int u = 0; u < 6; u++) {
            x[u] = erow[u * 32 + lane];
            ssq += x[u].x * x[u].x + x[u].y * x[u].y + x[u].z * x[u].z + x[u].w * x[u].w;
        }
        #pragma unroll
        for (int o = 16; o; o >>= 1) ssq += __shfl_xor_sync(0xffffffffu, ssq, o);
        const float invn = 1.f / fmaxf(sqrtf(ssq), EPS_);
        #pragma unroll
        for (int u = 0; u < 6; u++) {
            float v0 = x[u].x * invn, v1 = x[u].y * invn;
            float v2 = x[u].z * invn, v3 = x[u].w * invn;
            __nv_bfloat16 h0 = __float2bfloat16_rn(v0);
            __nv_bfloat16 h1 = __float2bfloat16_rn(v1);
            __nv_bfloat16 h2 = __float2bfloat16_rn(v2);
            __nv_bfloat16 h3 = __float2bfloat16_rn(v3);
            __nv_bfloat16 l0 = __float2bfloat16_rn(v0 - __bfloat162float(h0));
            __nv_bfloat16 l1 = __float2bfloat16_rn(v1 - __bfloat162float(h1));
            __nv_bfloat16 l2 = __float2bfloat16_rn(v2 - __bfloat162float(h2));
            __nv_bfloat16 l3 = __float2bfloat16_rn(v3 - __bfloat162float(h3));
            __nv_bfloat162 hp0(h0, h1), hp1(h2, h3), lp0(l0, l1), lp1(l2, l3);
            hrow[u * 32 + lane] = make_uint2(*(uint32_t*)&hp0, *(uint32_t*)&hp1);
            lrow[u * 32 + lane] = make_uint2(*(uint32_t*)&lp0, *(uint32_t*)&lp1);
        }
        return;
    }

    // ---------------- role 1: pooling ----------------
    const int b = blk / RPB, s = blk % RPB;
    uint32_t* ahr = (uint32_t*)&g_Ahi[(size_t)blk * H_];
    uint32_t* alr = (uint32_t*)&g_Alo[(size_t)blk * H_];

    __shared__ int   spos[64];
    __shared__ float red[8];

    int cnt = 0;
    if (s < S_) {
        if (tid < 64) spos[tid] = pos[b * T_ + s * 64 + tid];
        __syncthreads();
        const int target = s + 1;
        #pragma unroll 8
        for (int t = 0; t < 64; t++) cnt += (spos[t] == target);
    }

    if (cnt == 0) {
        #pragma unroll
        for (int k = 0; k < 2; k++) {
            int i = tid + k * 256;
            if (i < H_ / 2) { ahr[i] = 0u; alr[i] = 0u; }
        }
        if (tid == 0) g_valid[blk] = 0.f;
        return;
    }

    const int target = s + 1;
    const float* hb = hidden + ((size_t)b * T_ + (size_t)s * 64) * H_;
    float a0 = 0.f, a1 = 0.f, a2 = 0.f;
    #pragma unroll 8
    for (int t = 0; t < 64; t++) {
        float m = (spos[t] == target) ? 1.f : 0.f;
        const float* r = hb + (size_t)t * H_;
        a0 += m * r[tid];
        a1 += m * r[tid + 256];
        a2 += m * r[tid + 512];
    }
    const float inv_c = 1.f / (float)cnt;
    a0 *= inv_c; a1 *= inv_c; a2 *= inv_c;

    float ss = a0 * a0 + a1 * a1 + a2 * a2;
    #pragma unroll
    for (int o = 16; o; o >>= 1) ss += __shfl_down_sync(0xffffffffu, ss, o);
    if ((tid & 31) == 0) red[tid >> 5] = ss;
    __syncthreads();
    if (tid < 8) {
        float v = red[tid];
        #pragma unroll
        for (int o = 4; o; o >>= 1) v += __shfl_down_sync(0xffu, v, o);
        if (tid == 0) red[0] = v;
    }
    __syncthreads();

    const float scale = 1.f / (fmaxf(sqrtf(red[0]), EPS_) * TEMP_);
    float vals[3] = { a0 * scale, a1 * scale, a2 * scale };
    #pragma unroll
    for (int k = 0; k < 3; k++) {
        int c = tid + k * 256;
        float x = vals[k];
        __nv_bfloat16 h = __float2bfloat16_rn(x);
        __nv_bfloat16 l = __float2bfloat16_rn(x - __bfloat162float(h));
        g_Ahi[(size_t)blk * H_ + c] = h;
        g_Alo[(size_t)blk * H_ + c] = l;
    }
    if (tid == 0) g_valid[blk] = 1.f;
}

// ---------------------------------------------------------------------------
// Kernel 2: bf16 mma.sync GEMM + maxsim epilogue into global ordered-uint.
// grid = (MP/128 = 3, NP/128 = 391), 256 threads (8 warps, 2x4 m64n32 tiles),
// 3-stage cp.async pipeline, split-term MMAs reordered term-outermost.
// ---------------------------------------------------------------------------
__global__ __launch_bounds__(256, 1)
void gemm_mma() {
    extern __shared__ __align__(16) char dsm[];
    __shared__ unsigned s_red[6][BN];
    __shared__ float s_val[BM];

    const int tid  = threadIdx.x;
    const int wid  = tid >> 5;
    const int lane = tid & 31;
    const int wm   = wid >> 2;        // 0..1  (m64 tile)
    const int wn   = wid & 3;         // 0..3  (n32 tile)
    const int m0   = blockIdx.x * BM;
    const int n0   = blockIdx.y * BN;
    const int gbase = m0 / RPB;       // 0, 5, 10

    const uint32_t base = (smem_u32(dsm) + 1023u) & ~1023u;

    if (tid < BM) s_val[tid] = g_valid[m0 + tid];
    #pragma unroll
    for (int k = 0; k < 3; k++) {
        int i = tid + k * 256;
        if (i < 6 * BN) s_red[i >> 7][i & 127] = NEG_ORD;
    }

    auto issue_loads = [&](int kc, int stg) {
        const uint32_t sb = base + stg * STAGE_B;
        const __nv_bfloat16* srcs[4] = {
            g_Ahi + (size_t)m0 * H_, g_Alo + (size_t)m0 * H_,
            g_Ehi + (size_t)n0 * H_, g_Elo + (size_t)n0 * H_ };
        #pragma unroll
        for (int t = 0; t < 4; t++) {
            const uint32_t tb = sb + t * TILE_B;
            const __nv_bfloat16* src = srcs[t];
            #pragma unroll
            for (int j = 0; j < 4; j++) {
                int i = tid + j * 256;        // 0..1023
                int row = i >> 3, u = i & 7;
                cp16(tb + sw128((uint32_t)(row * 128 + u * 16)),
                     src + (size_t)row * H_ + kc * BK + u * 8);
            }
        }
        CP_COMMIT();
    };

    float acc[4][4][4];
    #pragma unroll
    for (int mi = 0; mi < 4; mi++)
        #pragma unroll
        for (int ni = 0; ni < 4; ni++)
            #pragma unroll
            for (int q = 0; q < 4; q++) acc[mi][ni][q] = 0.f;

    const uint32_t a_row = (uint32_t)(wm * 64 + ((lane >> 3) & 1) * 8 + (lane & 7)) * 128;
    const uint32_t a_u   = (uint32_t)((lane >> 4) & 1) * 16;
    const uint32_t b_row = (uint32_t)(wn * 32 + ((lane >> 4) & 1) * 8 + (lane & 7)) * 128;
    const uint32_t b_u   = (uint32_t)((lane >> 3) & 1) * 16;

    issue_loads(0, 0);
    issue_loads(1, 1);

    for (int kc = 0; kc < NKCH; kc++) {
        CP_WAIT(1);
        __syncthreads();
        if (kc + 2 < NKCH) issue_loads(kc + 2, (kc + 2) % NSTAGE);

        const uint32_t sb  = base + (kc % NSTAGE) * STAGE_B;
        const uint32_t Ahs = sb;
        const uint32_t Als = sb + TILE_B;
        const uint32_t Ehs = sb + 2 * TILE_B;
        const uint32_t Els = sb + 3 * TILE_B;

        #pragma unroll
        for (int s = 0; s < 4; s++) {
            const uint32_t ku = (uint32_t)(s * 32);
            uint32_t ah[4][4], al[4][4], bh[2][4], bl[2][4];
            #pragma unroll
            for (int mi = 0; mi < 4; mi++) {
                uint32_t off = sw128(a_row + (uint32_t)(mi * 16 * 128) + ku + a_u);
                ldsm_x4(ah[mi], Ahs + off);
                ldsm_x4(al[mi], Als + off);
            }
            #pragma unroll
            for (int nj = 0; nj < 2; nj++) {
                uint32_t off = sw128(b_row + (uint32_t)(nj * 16 * 128) + ku + b_u);
                ldsm_x4(bh[nj], Ehs + off);
                ldsm_x4(bl[nj], Els + off);
            }
            // term-outermost: 16 independent MMAs between accumulator reuses
            #pragma unroll
            for (int mi = 0; mi < 4; mi++)
                #pragma unroll
                for (int ni = 0; ni < 4; ni++)
                    mma16816(acc[mi][ni], ah[mi], &bh[ni >> 1][(ni & 1) * 2]);
            #pragma unroll
            for (int mi = 0; mi < 4; mi++)
                #pragma unroll
                for (int ni = 0; ni < 4; ni++)
                    mma16816(acc[mi][ni], al[mi], &bh[ni >> 1][(ni & 1) * 2]);
            #pragma unroll
            for (int mi = 0; mi < 4; mi++)
                #pragma unroll
                for (int ni = 0; ni < 4; ni++)
                    mma16816(acc[mi][ni], ah[mi], &bl[ni >> 1][(ni & 1) * 2]);
        }
    }

    // ---- epilogue: mask, per-session max via smem ordered atomicMax ----
    #pragma unroll
    for (int mi = 0; mi < 4; mi++) {
        const int r0 = wm * 64 + mi * 16 + (lane >> 2);
        const int r1 = r0 + 8;
        const bool ok0 = s_val[r0] > 0.5f;
        const bool ok1 = s_val[r1] > 0.5f;
        const int lg0 = (m0 + r0) / RPB - gbase;
        const int lg1 = (m0 + r1) / RPB - gbase;
        #pragma unroll
        for (int ni = 0; ni < 4; ni++) {
            const int c = wn * 32 + ni * 8 + (lane & 3) * 2;
            unsigned u0 = ok0 ? f2o(acc[mi][ni][0]) : NEG_ORD;
            unsigned u1 = ok0 ? f2o(acc[mi][ni][1]) : NEG_ORD;
            unsigned u2 = ok1 ? f2o(acc[mi][ni][2]) : NEG_ORD;
            unsigned u3 = ok1 ? f2o(acc[mi][ni][3]) : NEG_ORD;
            if (lg0 == lg1) {
                atomicMax(&s_red[lg0][c],     u0 > u2 ? u0 : u2);
                atomicMax(&s_red[lg0][c + 1], u1 > u3 ? u1 : u3);
            } else {
                atomicMax(&s_red[lg0][c],     u0);
                atomicMax(&s_red[lg0][c + 1], u1);
                atomicMax(&s_red[lg1][c],     u2);
                atomicMax(&s_red[lg1][c + 1], u3);
            }
        }
    }
    __syncthreads();

    // combine into global ordered-uint accumulator (groups may straddle tiles)
    #pragma unroll
    for (int k = 0; k < 3; k++) {
        int i = tid + k * 256;
        if (i < 6 * BN) {
            int lg = i >> 7, c = i & 127;
            int g = gbase + lg;
            unsigned v = s_red[lg][c];
            if (g < B_ && v != NEG_ORD)
                atomicMax(&g_outU[(size_t)g * NP + n0 + c], v);
        }
    }
}

// ---------------------------------------------------------------------------
// Kernel 3: finalize -> decode ordered-uint to float output.
// ---------------------------------------------------------------------------
__global__ __launch_bounds__(256)
void finalize_kernel(float* __restrict__ out) {
    int i = blockIdx.x * 256 + threadIdx.x;
    if (i < B_ * NI) {
        int b = i / NI, n = i - b * NI;
        out[i] = o2f(g_outU[(size_t)b * NP + n]);
    }
}

// ---------------------------------------------------------------------------
// Launch
// ---------------------------------------------------------------------------
extern "C" void kernel_launch(void* const* d_in, const int* in_sizes, int n_in,
                              void* d_out, int out_size) {
    const float* hidden = (const float*)d_in[0];   // [16,1280,768] f32
    const float* emb    = (const float*)d_in[1];   // [50000,768] f32
    const int*   pos    = (const int*)  d_in[3];   // [16,1280] i32
    float* out = (float*)d_out;                    // [16,50000] f32

    cudaFuncSetAttribute(gemm_mma, cudaFuncAttributeMaxDynamicSharedMemorySize, DSMEM_BYTES);

    prep_kernel<<<PREP_GRID, 256>>>(hidden, pos, emb);
    gemm_mma<<<dim3(MP / BM, NP / BN), 256, DSMEM_BYTES>>>();
    finalize_kernel<<<(B_ * NI + 255) / 256, 256>>>(out);
}

// round 11
// speedup vs baseline: 1.3113x; 1.0212x over previous
#include <cuda_runtime.h>
#include <cuda_bf16.h>
#include <math_constants.h>
#include <cstdint>

// ---------------- Problem constants ----------------
#define B_    16
#define S_    20
#define RPB   24               // rows per batch session group (pad 20 -> 24)
#define T_    1280
#define H_    768
#define NI    50000
#define NP    50048            // N padded to multiple of 128
#define MP    (B_ * RPB)       // 384 padded M rows
#define TEMP_ 0.05f
#define EPS_  1e-8f

// ---------------- GEMM config ----------------
#define BM 128
#define BN 128
#define BK 64
#define NSTAGE 3
#define NKCH (H_ / BK)          // 12
#define TILE_B   16384          // one 128x64 bf16 tile (128 rows x 128B)
#define STAGE_B  (4 * TILE_B)   // Ahi, Alo, Ehi, Elo
#define DSMEM_BYTES (NSTAGE * STAGE_B + 1024)   // 197632
#define GTHREADS 512

#define NEG_ORD 0x007FFFFFu     // f2o(-inf)

// ---------------- Scratch (device globals) ----------------
__device__ __nv_bfloat16 g_Ahi[(size_t)MP * H_];
__device__ __nv_bfloat16 g_Alo[(size_t)MP * H_];
__device__ __nv_bfloat16 g_Ehi[(size_t)NP * H_];   // prescaled by 1/||e||
__device__ __nv_bfloat16 g_Elo[(size_t)NP * H_];
__device__ float         g_valid[MP];
__device__ unsigned      g_outU[(size_t)B_ * NP];  // ordered-uint maxsim accumulator

// ---------------- helpers ----------------
static __device__ __forceinline__ uint32_t smem_u32(const void* p) {
    uint32_t a;
    asm("{ .reg .u64 t; cvta.to.shared.u64 t, %1; cvt.u32.u64 %0, t; }" : "=r"(a) : "l"(p));
    return a;
}
static __device__ __forceinline__ uint32_t sw128(uint32_t o) { return o ^ ((o >> 3) & 0x70); }

static __device__ __forceinline__ void cp16(uint32_t dst, const void* src) {
    asm volatile("cp.async.cg.shared.global [%0], [%1], 16;" :: "r"(dst), "l"(src));
}
#define CP_COMMIT()   asm volatile("cp.async.commit_group;" ::: "memory")
#define CP_WAIT(n)    asm volatile("cp.async.wait_group %0;" :: "n"(n) : "memory")

static __device__ __forceinline__ void ldsm_x4(uint32_t* r, uint32_t addr) {
    asm volatile("ldmatrix.sync.aligned.m8n8.x4.shared.b16 {%0,%1,%2,%3}, [%4];"
        : "=r"(r[0]), "=r"(r[1]), "=r"(r[2]), "=r"(r[3]) : "r"(addr));
}
static __device__ __forceinline__ void mma16816(float* d, const uint32_t* a, const uint32_t* b) {
    asm volatile("mma.sync.aligned.m16n8k16.row.col.f32.bf16.bf16.f32 "
        "{%0,%1,%2,%3}, {%4,%5,%6,%7}, {%8,%9}, {%0,%1,%2,%3};"
        : "+f"(d[0]), "+f"(d[1]), "+f"(d[2]), "+f"(d[3])
        : "r"(a[0]), "r"(a[1]), "r"(a[2]), "r"(a[3]), "r"(b[0]), "r"(b[1]));
}
static __device__ __forceinline__ unsigned f2o(float x) {
    unsigned u = __float_as_uint(x);
    return (u >> 31) ? ~u : (u | 0x80000000u);
}
static __device__ __forceinline__ float o2f(unsigned u) {
    return (u >> 31) ? __uint_as_float(u & 0x7fffffffu) : __uint_as_float(~u);
}

// ---------------------------------------------------------------------------
// Kernel 1 (fused prep): three block roles.
//   blocks [0, MP)            : pooling -> bf16 hi/lo A + validity
//   blocks [MP, MP + NP/8)    : E fp32 -> normalize -> bf16 hi/lo (8 rows/blk)
//   blocks [MP+NP/8, ...)     : init g_outU to NEG_ORD
// ---------------------------------------------------------------------------
#define EPREP_BLKS (NP / 8)                 // 6256
#define INIT_BLKS  ((B_ * NP + 2047) / 2048) // 392
#define PREP_GRID  (MP + EPREP_BLKS + INIT_BLKS)

__global__ __launch_bounds__(256)
void prep_kernel(const float* __restrict__ hidden,
                 const int*   __restrict__ pos,
                 const float* __restrict__ emb) {
    const int blk = blockIdx.x;
    const int tid = threadIdx.x;

    // ---------------- role 3: output-accumulator init ----------------
    if (blk >= MP + EPREP_BLKS) {
        const int rb = blk - MP - EPREP_BLKS;
        #pragma unroll
        for (int k = 0; k < 8; k++) {
            int idx = rb * 2048 + k * 256 + tid;
            if (idx < B_ * NP) g_outU[idx] = NEG_ORD;
        }
        return;
    }

    // ---------------- role 2: E prep ----------------
    if (blk >= MP) {
        const int n = (blk - MP) * 8 + (tid >> 5);
        const int lane = tid & 31;
        uint2* hrow = (uint2*)&g_Ehi[(size_t)n * H_];
        uint2* lrow = (uint2*)&g_Elo[(size_t)n * H_];
        if (n >= NI) {
            #pragma unroll
            for (int u = 0; u < 6; u++) {
                hrow[u * 32 + lane] = make_uint2(0u, 0u);
                lrow[u * 32 + lane] = make_uint2(0u, 0u);
            }
            return;
        }
        const float4* erow = (const float4*)&emb[(size_t)n * H_];
        float4 x[6];
        float ssq = 0.f;
        #pragma unroll
        for (int u = 0; u < 6; u++) {
            x[u] = erow[u * 32 + lane];
            ssq += x[u].x * x[u].x + x[u].y * x[u].y + x[u].z * x[u].z + x[u].w * x[u].w;
        }
        #pragma unroll
        for (int o = 16; o; o >>= 1) ssq += __shfl_xor_sync(0xffffffffu, ssq, o);
        const float invn = 1.f / fmaxf(sqrtf(ssq), EPS_);
        #pragma unroll
        for (int u = 0; u < 6; u++) {
            float v0 = x[u].x * invn, v1 = x[u].y * invn;
            float v2 = x[u].z * invn, v3 = x[u].w * invn;
            __nv_bfloat16 h0 = __float2bfloat16_rn(v0);
            __nv_bfloat16 h1 = __float2bfloat16_rn(v1);
            __nv_bfloat16 h2 = __float2bfloat16_rn(v2);
            __nv_bfloat16 h3 = __float2bfloat16_rn(v3);
            __nv_bfloat16 l0 = __float2bfloat16_rn(v0 - __bfloat162float(h0));
            __nv_bfloat16 l1 = __float2bfloat16_rn(v1 - __bfloat162float(h1));
            __nv_bfloat16 l2 = __float2bfloat16_rn(v2 - __bfloat162float(h2));
            __nv_bfloat16 l3 = __float2bfloat16_rn(v3 - __bfloat162float(h3));
            __nv_bfloat162 hp0(h0, h1), hp1(h2, h3), lp0(l0, l1), lp1(l2, l3);
            hrow[u * 32 + lane] = make_uint2(*(uint32_t*)&hp0, *(uint32_t*)&hp1);
            lrow[u * 32 + lane] = make_uint2(*(uint32_t*)&lp0, *(uint32_t*)&lp1);
        }
        return;
    }

    // ---------------- role 1: pooling ----------------
    const int b = blk / RPB, s = blk % RPB;
    uint32_t* ahr = (uint32_t*)&g_Ahi[(size_t)blk * H_];
    uint32_t* alr = (uint32_t*)&g_Alo[(size_t)blk * H_];

    __shared__ int   spos[64];
    __shared__ float red[8];

    int cnt = 0;
    if (s < S_) {
        if (tid < 64) spos[tid] = pos[b * T_ + s * 64 + tid];
        __syncthreads();
        const int target = s + 1;
        #pragma unroll 8
        for (int t = 0; t < 64; t++) cnt += (spos[t] == target);
    }

    if (cnt == 0) {
        #pragma unroll
        for (int k = 0; k < 2; k++) {
            int i = tid + k * 256;
            if (i < H_ / 2) { ahr[i] = 0u; alr[i] = 0u; }
        }
        if (tid == 0) g_valid[blk] = 0.f;
        return;
    }

    const int target = s + 1;
    const float* hb = hidden + ((size_t)b * T_ + (size_t)s * 64) * H_;
    float a0 = 0.f, a1 = 0.f, a2 = 0.f;
    #pragma unroll 8
    for (int t = 0; t < 64; t++) {
        float m = (spos[t] == target) ? 1.f : 0.f;
        const float* r = hb + (size_t)t * H_;
        a0 += m * r[tid];
        a1 += m * r[tid + 256];
        a2 += m * r[tid + 512];
    }
    const float inv_c = 1.f / (float)cnt;
    a0 *= inv_c; a1 *= inv_c; a2 *= inv_c;

    float ss = a0 * a0 + a1 * a1 + a2 * a2;
    #pragma unroll
    for (int o = 16; o; o >>= 1) ss += __shfl_down_sync(0xffffffffu, ss, o);
    if ((tid & 31) == 0) red[tid >> 5] = ss;
    __syncthreads();
    if (tid < 8) {
        float v = red[tid];
        #pragma unroll
        for (int o = 4; o; o >>= 1) v += __shfl_down_sync(0xffu, v, o);
        if (tid == 0) red[0] = v;
    }
    __syncthreads();

    const float scale = 1.f / (fmaxf(sqrtf(red[0]), EPS_) * TEMP_);
    float vals[3] = { a0 * scale, a1 * scale, a2 * scale };
    #pragma unroll
    for (int k = 0; k < 3; k++) {
        int c = tid + k * 256;
        float x = vals[k];
        __nv_bfloat16 h = __float2bfloat16_rn(x);
        __nv_bfloat16 l = __float2bfloat16_rn(x - __bfloat162float(h));
        g_Ahi[(size_t)blk * H_ + c] = h;
        g_Alo[(size_t)blk * H_ + c] = l;
    }
    if (tid == 0) g_valid[blk] = 1.f;
}

// ---------------------------------------------------------------------------
// Kernel 2: bf16 mma.sync GEMM + maxsim epilogue into global ordered-uint.
// grid = (MP/128 = 3, NP/128 = 391), 512 threads = 16 warps (4x4 m32n32
// warp tiles -> 4 warps/SMSP for latency hiding), 3-stage cp.async pipeline.
// ---------------------------------------------------------------------------
__global__ __launch_bounds__(GTHREADS, 1)
void gemm_mma() {
    extern __shared__ __align__(16) char dsm[];
    __shared__ unsigned s_red[6][BN];
    __shared__ float s_val[BM];

    const int tid  = threadIdx.x;
    const int wid  = tid >> 5;
    const int lane = tid & 31;
    const int wm   = wid >> 2;        // 0..3  (m32 tile)
    const int wn   = wid & 3;         // 0..3  (n32 tile)
    const int m0   = blockIdx.x * BM;
    const int n0   = blockIdx.y * BN;
    const int gbase = m0 / RPB;       // 0, 5, 10

    const uint32_t base = (smem_u32(dsm) + 1023u) & ~1023u;

    if (tid < BM) s_val[tid] = g_valid[m0 + tid];
    #pragma unroll
    for (int k = 0; k < 2; k++) {
        int i = tid + k * GTHREADS;
        if (i < 6 * BN) s_red[i >> 7][i & 127] = NEG_ORD;
    }

    auto issue_loads = [&](int kc, int stg) {
        const uint32_t sb = base + stg * STAGE_B;
        const __nv_bfloat16* srcs[4] = {
            g_Ahi + (size_t)m0 * H_, g_Alo + (size_t)m0 * H_,
            g_Ehi + (size_t)n0 * H_, g_Elo + (size_t)n0 * H_ };
        #pragma unroll
        for (int t = 0; t < 4; t++) {
            const uint32_t tb = sb + t * TILE_B;
            const __nv_bfloat16* src = srcs[t];
            #pragma unroll
            for (int j = 0; j < 2; j++) {
                int i = tid + j * GTHREADS;   // 0..1023
                int row = i >> 3, u = i & 7;
                cp16(tb + sw128((uint32_t)(row * 128 + u * 16)),
                     src + (size_t)row * H_ + kc * BK + u * 8);
            }
        }
        CP_COMMIT();
    };

    float acc[2][4][4];
    #pragma unroll
    for (int mi = 0; mi < 2; mi++)
        #pragma unroll
        for (int ni = 0; ni < 4; ni++)
            #pragma unroll
            for (int q = 0; q < 4; q++) acc[mi][ni][q] = 0.f;

    // per-lane ldmatrix row offsets (bytes), within a tile
    const uint32_t a_row = (uint32_t)(wm * 32 + (lane & 15)) * 128;
    const uint32_t a_u   = (uint32_t)((lane >> 4) & 1) * 16;
    const uint32_t b_row = (uint32_t)(wn * 32 + ((lane >> 4) & 1) * 8 + (lane & 7)) * 128;
    const uint32_t b_u   = (uint32_t)((lane >> 3) & 1) * 16;

    issue_loads(0, 0);
    issue_loads(1, 1);

    for (int kc = 0; kc < NKCH; kc++) {
        CP_WAIT(1);
        __syncthreads();
        if (kc + 2 < NKCH) issue_loads(kc + 2, (kc + 2) % NSTAGE);

        const uint32_t sb  = base + (kc % NSTAGE) * STAGE_B;
        const uint32_t Ahs = sb;
        const uint32_t Als = sb + TILE_B;
        const uint32_t Ehs = sb + 2 * TILE_B;
        const uint32_t Els = sb + 3 * TILE_B;

        #pragma unroll
        for (int s = 0; s < 4; s++) {
            const uint32_t ku = (uint32_t)(s * 32);
            uint32_t ah[2][4], al[2][4], bh[2][4], bl[2][4];
            #pragma unroll
            for (int mi = 0; mi < 2; mi++) {
                uint32_t off = sw128(a_row + (uint32_t)(mi * 16 * 128) + ku + a_u);
                ldsm_x4(ah[mi], Ahs + off);
                ldsm_x4(al[mi], Als + off);
            }
            #pragma unroll
            for (int nj = 0; nj < 2; nj++) {
                uint32_t off = sw128(b_row + (uint32_t)(nj * 16 * 128) + ku + b_u);
                ldsm_x4(bh[nj], Ehs + off);
                ldsm_x4(bl[nj], Els + off);
            }
            // term-outermost: 8 independent MMAs between accumulator reuses
            #pragma unroll
            for (int mi = 0; mi < 2; mi++)
                #pragma unroll
                for (int ni = 0; ni < 4; ni++)
                    mma16816(acc[mi][ni], ah[mi], &bh[ni >> 1][(ni & 1) * 2]);
            #pragma unroll
            for (int mi = 0; mi < 2; mi++)
                #pragma unroll
                for (int ni = 0; ni < 4; ni++)
                    mma16816(acc[mi][ni], al[mi], &bh[ni >> 1][(ni & 1) * 2]);
            #pragma unroll
            for (int mi = 0; mi < 2; mi++)
                #pragma unroll
                for (int ni = 0; ni < 4; ni++)
                    mma16816(acc[mi][ni], ah[mi], &bl[ni >> 1][(ni & 1) * 2]);
        }
    }

    // ---- epilogue: mask, per-session max via smem ordered atomicMax ----
    #pragma unroll
    for (int mi = 0; mi < 2; mi++) {
        const int r0 = wm * 32 + mi * 16 + (lane >> 2);
        const int r1 = r0 + 8;
        const bool ok0 = s_val[r0] > 0.5f;
        const bool ok1 = s_val[r1] > 0.5f;
        const int lg0 = (m0 + r0) / RPB - gbase;
        const int lg1 = (m0 + r1) / RPB - gbase;
        #pragma unroll
        for (int ni = 0; ni < 4; ni++) {
            const int c = wn * 32 + ni * 8 + (lane & 3) * 2;
            unsigned u0 = ok0 ? f2o(acc[mi][ni][0]) : NEG_ORD;
            unsigned u1 = ok0 ? f2o(acc[mi][ni][1]) : NEG_ORD;
            unsigned u2 = ok1 ? f2o(acc[mi][ni][2]) : NEG_ORD;
            unsigned u3 = ok1 ? f2o(acc[mi][ni][3]) : NEG_ORD;
            if (lg0 == lg1) {
                atomicMax(&s_red[lg0][c],     u0 > u2 ? u0 : u2);
                atomicMax(&s_red[lg0][c + 1], u1 > u3 ? u1 : u3);
            } else {
                atomicMax(&s_red[lg0][c],     u0);
                atomicMax(&s_red[lg0][c + 1], u1);
                atomicMax(&s_red[lg1][c],     u2);
                atomicMax(&s_red[lg1][c + 1], u3);
            }
        }
    }
    __syncthreads();

    // combine into global ordered-uint accumulator (groups may straddle tiles)
    #pragma unroll
    for (int k = 0; k < 2; k++) {
        int i = tid + k * GTHREADS;
        if (i < 6 * BN) {
            int lg = i >> 7, c = i & 127;
            int g = gbase + lg;
            unsigned v = s_red[lg][c];
            if (g < B_ && v != NEG_ORD)
                atomicMax(&g_outU[(size_t)g * NP + n0 + c], v);
        }
    }
}

// ---------------------------------------------------------------------------
// Kernel 3: finalize -> decode ordered-uint to float output.
// ---------------------------------------------------------------------------
__global__ __launch_bounds__(256)
void finalize_kernel(float* __restrict__ out) {
    int i = blockIdx.x * 256 + threadIdx.x;
    if (i < B_ * NI) {
        int b = i / NI, n = i - b * NI;
        out[i] = o2f(g_outU[(size_t)b * NP + n]);
    }
}

// ---------------------------------------------------------------------------
// Launch
// ---------------------------------------------------------------------------
extern "C" void kernel_launch(void* const* d_in, const int* in_sizes, int n_in,
                              void* d_out, int out_size) {
    const float* hidden = (const float*)d_in[0];   // [16,1280,768] f32
    const float* emb    = (const float*)d_in[1];   // [50000,768] f32
    const int*   pos    = (const int*)  d_in[3];   // [16,1280] i32
    float* out = (float*)d_out;                    // [16,50000] f32

    cudaFuncSetAttribute(gemm_mma, cudaFuncAttributeMaxDynamicSharedMemorySize, DSMEM_BYTES);

    prep_kernel<<<PREP_GRID, 256>>>(hidden, pos, emb);
    gemm_mma<<<dim3(MP / BM, NP / BN), GTHREADS, DSMEM_BYTES>>>();
    finalize_kernel<<<(B_ * NI + 255) / 256, 256>>>(out);
}

// round 12
// speedup vs baseline: 2.0378x; 1.5541x over previous
#include <cuda_runtime.h>
#include <cuda_fp16.h>
#include <math_constants.h>
#include <cstdint>

// ---------------- Problem constants ----------------
#define B_    16
#define S_    20
#define RPB   24               // rows per batch session group (pad 20 -> 24)
#define T_    1280
#define H_    768
#define NI    50000
#define NP    50048            // N padded to multiple of 128
#define MP    (B_ * RPB)       // 384 padded M rows
#define TEMP_ 0.05f
#define EPS_  1e-8f

// ---------------- GEMM config ----------------
#define BM 128
#define BN 128
#define BK 64
#define NSTAGE 3
#define NKCH (H_ / BK)          // 12
#define TILE_B   16384          // one 128x64 fp16 tile (128 rows x 128B)
#define STAGE_B  (2 * TILE_B)   // A, E
#define DSMEM_BYTES (NSTAGE * STAGE_B + 1024)   // 99328

#define NEG_ORD 0x007FFFFFu     // f2o(-inf)

// ---------------- Scratch (device globals) ----------------
__device__ __half   g_Ahf[(size_t)MP * H_];    // pooled, normalized, /TEMP
__device__ __half   g_Ehf[(size_t)NP * H_];    // prescaled by 1/||e||
__device__ float    g_valid[MP];
__device__ unsigned g_outU[(size_t)B_ * NP];   // ordered-uint maxsim accumulator

// ---------------- helpers ----------------
static __device__ __forceinline__ uint32_t smem_u32(const void* p) {
    uint32_t a;
    asm("{ .reg .u64 t; cvta.to.shared.u64 t, %1; cvt.u32.u64 %0, t; }" : "=r"(a) : "l"(p));
    return a;
}
static __device__ __forceinline__ uint32_t sw128(uint32_t o) { return o ^ ((o >> 3) & 0x70); }

static __device__ __forceinline__ void cp16(uint32_t dst, const void* src) {
    asm volatile("cp.async.cg.shared.global [%0], [%1], 16;" :: "r"(dst), "l"(src));
}
#define CP_COMMIT()   asm volatile("cp.async.commit_group;" ::: "memory")
#define CP_WAIT(n)    asm volatile("cp.async.wait_group %0;" :: "n"(n) : "memory")

static __device__ __forceinline__ void ldsm_x4(uint32_t* r, uint32_t addr) {
    asm volatile("ldmatrix.sync.aligned.m8n8.x4.shared.b16 {%0,%1,%2,%3}, [%4];"
        : "=r"(r[0]), "=r"(r[1]), "=r"(r[2]), "=r"(r[3]) : "r"(addr));
}
static __device__ __forceinline__ void mma16816(float* d, const uint32_t* a, const uint32_t* b) {
    asm volatile("mma.sync.aligned.m16n8k16.row.col.f32.f16.f16.f32 "
        "{%0,%1,%2,%3}, {%4,%5,%6,%7}, {%8,%9}, {%0,%1,%2,%3};"
        : "+f"(d[0]), "+f"(d[1]), "+f"(d[2]), "+f"(d[3])
        : "r"(a[0]), "r"(a[1]), "r"(a[2]), "r"(a[3]), "r"(b[0]), "r"(b[1]));
}
static __device__ __forceinline__ unsigned f2o(float x) {
    unsigned u = __float_as_uint(x);
    return (u >> 31) ? ~u : (u | 0x80000000u);
}
static __device__ __forceinline__ float o2f(unsigned u) {
    return (u >> 31) ? __uint_as_float(u & 0x7fffffffu) : __uint_as_float(~u);
}

// ---------------------------------------------------------------------------
// Kernel 1 (fused prep): three block roles.
//   blocks [0, MP)            : pooling -> fp16 A + validity
//   blocks [MP, MP + NP/8)    : E fp32 -> normalize -> fp16 (8 rows/blk)
//   blocks [MP+NP/8, ...)     : init g_outU to NEG_ORD
// ---------------------------------------------------------------------------
#define EPREP_BLKS (NP / 8)                 // 6256
#define INIT_BLKS  ((B_ * NP + 2047) / 2048) // 392
#define PREP_GRID  (MP + EPREP_BLKS + INIT_BLKS)

__global__ __launch_bounds__(256)
void prep_kernel(const float* __restrict__ hidden,
                 const int*   __restrict__ pos,
                 const float* __restrict__ emb) {
    const int blk = blockIdx.x;
    const int tid = threadIdx.x;

    // ---------------- role 3: output-accumulator init ----------------
    if (blk >= MP + EPREP_BLKS) {
        const int rb = blk - MP - EPREP_BLKS;
        #pragma unroll
        for (int k = 0; k < 8; k++) {
            int idx = rb * 2048 + k * 256 + tid;
            if (idx < B_ * NP) g_outU[idx] = NEG_ORD;
        }
        return;
    }

    // ---------------- role 2: E prep ----------------
    if (blk >= MP) {
        const int n = (blk - MP) * 8 + (tid >> 5);
        const int lane = tid & 31;
        uint2* hrow = (uint2*)&g_Ehf[(size_t)n * H_];   // 8B = 4 halves
        if (n >= NI) {
            #pragma unroll
            for (int u = 0; u < 6; u++)
                hrow[u * 32 + lane] = make_uint2(0u, 0u);
            return;
        }
        const float4* erow = (const float4*)&emb[(size_t)n * H_];
        float4 x[6];
        float ssq = 0.f;
        #pragma unroll
        for (int u = 0; u < 6; u++) {
            x[u] = erow[u * 32 + lane];
            ssq += x[u].x * x[u].x + x[u].y * x[u].y + x[u].z * x[u].z + x[u].w * x[u].w;
        }
        #pragma unroll
        for (int o = 16; o; o >>= 1) ssq += __shfl_xor_sync(0xffffffffu, ssq, o);
        const float invn = 1.f / fmaxf(sqrtf(ssq), EPS_);
        #pragma unroll
        for (int u = 0; u < 6; u++) {
            __half2 p0 = __floats2half2_rn(x[u].x * invn, x[u].y * invn);
            __half2 p1 = __floats2half2_rn(x[u].z * invn, x[u].w * invn);
            hrow[u * 32 + lane] = make_uint2(*(uint32_t*)&p0, *(uint32_t*)&p1);
        }
        return;
    }

    // ---------------- role 1: pooling ----------------
    const int b = blk / RPB, s = blk % RPB;
    uint32_t* ahr = (uint32_t*)&g_Ahf[(size_t)blk * H_];   // 384 uint32

    __shared__ int   spos[64];
    __shared__ float red[8];

    int cnt = 0;
    if (s < S_) {
        if (tid < 64) spos[tid] = pos[b * T_ + s * 64 + tid];
        __syncthreads();
        const int target = s + 1;
        #pragma unroll 8
        for (int t = 0; t < 64; t++) cnt += (spos[t] == target);
    }

    if (cnt == 0) {
        #pragma unroll
        for (int k = 0; k < 2; k++) {
            int i = tid + k * 256;
            if (i < H_ / 2) ahr[i] = 0u;
        }
        if (tid == 0) g_valid[blk] = 0.f;
        return;
    }

    const int target = s + 1;
    const float* hb = hidden + ((size_t)b * T_ + (size_t)s * 64) * H_;
    float a0 = 0.f, a1 = 0.f, a2 = 0.f;
    #pragma unroll 8
    for (int t = 0; t < 64; t++) {
        float m = (spos[t] == target) ? 1.f : 0.f;
        const float* r = hb + (size_t)t * H_;
        a0 += m * r[tid];
        a1 += m * r[tid + 256];
        a2 += m * r[tid + 512];
    }
    const float inv_c = 1.f / (float)cnt;
    a0 *= inv_c; a1 *= inv_c; a2 *= inv_c;

    float ss = a0 * a0 + a1 * a1 + a2 * a2;
    #pragma unroll
    for (int o = 16; o; o >>= 1) ss += __shfl_down_sync(0xffffffffu, ss, o);
    if ((tid & 31) == 0) red[tid >> 5] = ss;
    __syncthreads();
    if (tid < 8) {
        float v = red[tid];
        #pragma unroll
        for (int o = 4; o; o >>= 1) v += __shfl_down_sync(0xffu, v, o);
        if (tid == 0) red[0] = v;
    }
    __syncthreads();

    const float scale = 1.f / (fmaxf(sqrtf(red[0]), EPS_) * TEMP_);
    g_Ahf[(size_t)blk * H_ + tid]       = __float2half_rn(a0 * scale);
    g_Ahf[(size_t)blk * H_ + tid + 256] = __float2half_rn(a1 * scale);
    g_Ahf[(size_t)blk * H_ + tid + 512] = __float2half_rn(a2 * scale);
    if (tid == 0) g_valid[blk] = 1.f;
}

// ---------------------------------------------------------------------------
// Kernel 2: fp16 single-term mma.sync GEMM + maxsim epilogue.
// grid = (MP/128 = 3, NP/128 = 391), 256 threads (8 warps, 2x4 m64n32 tiles),
// 3-stage cp.async pipeline, 2 CTAs/SM.
// ---------------------------------------------------------------------------
__global__ __launch_bounds__(256, 2)
void gemm_mma() {
    extern __shared__ __align__(16) char dsm[];
    __shared__ unsigned s_red[6][BN];
    __shared__ float s_val[BM];

    const int tid  = threadIdx.x;
    const int wid  = tid >> 5;
    const int lane = tid & 31;
    const int wm   = wid >> 2;        // 0..1  (m64 tile)
    const int wn   = wid & 3;         // 0..3  (n32 tile)
    const int m0   = blockIdx.x * BM;
    const int n0   = blockIdx.y * BN;
    const int gbase = m0 / RPB;       // 0, 5, 10

    const uint32_t base = (smem_u32(dsm) + 1023u) & ~1023u;

    if (tid < BM) s_val[tid] = g_valid[m0 + tid];
    #pragma unroll
    for (int k = 0; k < 3; k++) {
        int i = tid + k * 256;
        if (i < 6 * BN) s_red[i >> 7][i & 127] = NEG_ORD;
    }

    auto issue_loads = [&](int kc, int stg) {
        const uint32_t sb = base + stg * STAGE_B;
        const __half* srcs[2] = { g_Ahf + (size_t)m0 * H_, g_Ehf + (size_t)n0 * H_ };
        #pragma unroll
        for (int t = 0; t < 2; t++) {
            const uint32_t tb = sb + t * TILE_B;
            const __half* src = srcs[t];
            #pragma unroll
            for (int j = 0; j < 4; j++) {
                int i = tid + j * 256;        // 0..1023
                int row = i >> 3, u = i & 7;
                cp16(tb + sw128((uint32_t)(row * 128 + u * 16)),
                     src + (size_t)row * H_ + kc * BK + u * 8);
            }
        }
        CP_COMMIT();
    };

    float acc[4][4][4];
    #pragma unroll
    for (int mi = 0; mi < 4; mi++)
        #pragma unroll
        for (int ni = 0; ni < 4; ni++)
            #pragma unroll
            for (int q = 0; q < 4; q++) acc[mi][ni][q] = 0.f;

    // per-lane ldmatrix row offsets (bytes), within a tile
    const uint32_t a_row = (uint32_t)(wm * 64 + ((lane >> 3) & 1) * 8 + (lane & 7)) * 128;
    const uint32_t a_u   = (uint32_t)((lane >> 4) & 1) * 16;
    const uint32_t b_row = (uint32_t)(wn * 32 + ((lane >> 4) & 1) * 8 + (lane & 7)) * 128;
    const uint32_t b_u   = (uint32_t)((lane >> 3) & 1) * 16;

    issue_loads(0, 0);
    issue_loads(1, 1);

    for (int kc = 0; kc < NKCH; kc++) {
        CP_WAIT(1);
        __syncthreads();
        if (kc + 2 < NKCH) issue_loads(kc + 2, (kc + 2) % NSTAGE);

        const uint32_t sb = base + (kc % NSTAGE) * STAGE_B;
        const uint32_t As = sb;
        const uint32_t Es = sb + TILE_B;

        #pragma unroll
        for (int s = 0; s < 4; s++) {
            const uint32_t ku = (uint32_t)(s * 32);
            uint32_t ah[4][4], bh[2][4];
            #pragma unroll
            for (int mi = 0; mi < 4; mi++)
                ldsm_x4(ah[mi], As + sw128(a_row + (uint32_t)(mi * 16 * 128) + ku + a_u));
            #pragma unroll
            for (int nj = 0; nj < 2; nj++)
                ldsm_x4(bh[nj], Es + sw128(b_row + (uint32_t)(nj * 16 * 128) + ku + b_u));
            #pragma unroll
            for (int mi = 0; mi < 4; mi++)
                #pragma unroll
                for (int ni = 0; ni < 4; ni++)
                    mma16816(acc[mi][ni], ah[mi], &bh[ni >> 1][(ni & 1) * 2]);
        }
    }

    // ---- epilogue: mask, per-session max via smem ordered atomicMax ----
    #pragma unroll
    for (int mi = 0; mi < 4; mi++) {
        const int r0 = wm * 64 + mi * 16 + (lane >> 2);
        const int r1 = r0 + 8;
        const bool ok0 = s_val[r0] > 0.5f;
        const bool ok1 = s_val[r1] > 0.5f;
        const int lg0 = (m0 + r0) / RPB - gbase;
        const int lg1 = (m0 + r1) / RPB - gbase;
        #pragma unroll
        for (int ni = 0; ni < 4; ni++) {
            const int c = wn * 32 + ni * 8 + (lane & 3) * 2;
            unsigned u0 = ok0 ? f2o(acc[mi][ni][0]) : NEG_ORD;
            unsigned u1 = ok0 ? f2o(acc[mi][ni][1]) : NEG_ORD;
            unsigned u2 = ok1 ? f2o(acc[mi][ni][2]) : NEG_ORD;
            unsigned u3 = ok1 ? f2o(acc[mi][ni][3]) : NEG_ORD;
            if (lg0 == lg1) {
                atomicMax(&s_red[lg0][c],     u0 > u2 ? u0 : u2);
                atomicMax(&s_red[lg0][c + 1], u1 > u3 ? u1 : u3);
            } else {
                atomicMax(&s_red[lg0][c],     u0);
                atomicMax(&s_red[lg0][c + 1], u1);
                atomicMax(&s_red[lg1][c],     u2);
                atomicMax(&s_red[lg1][c + 1], u3);
            }
        }
    }
    __syncthreads();

    // combine into global ordered-uint accumulator (groups may straddle tiles)
    #pragma unroll
    for (int k = 0; k < 3; k++) {
        int i = tid + k * 256;
        if (i < 6 * BN) {
            int lg = i >> 7, c = i & 127;
            int g = gbase + lg;
            unsigned v = s_red[lg][c];
            if (g < B_ && v != NEG_ORD)
                atomicMax(&g_outU[(size_t)g * NP + n0 + c], v);
        }
    }
}

// ---------------------------------------------------------------------------
// Kernel 3: finalize -> decode ordered-uint to float output.
// ---------------------------------------------------------------------------
__global__ __launch_bounds__(256)
void finalize_kernel(float* __restrict__ out) {
    int i = blockIdx.x * 256 + threadIdx.x;
    if (i < B_ * NI) {
        int b = i / NI, n = i - b * NI;
        out[i] = o2f(g_outU[(size_t)b * NP + n]);
    }
}

// ---------------------------------------------------------------------------
// Launch
// ---------------------------------------------------------------------------
extern "C" void kernel_launch(void* const* d_in, const int* in_sizes, int n_in,
                              void* d_out, int out_size) {
    const float* hidden = (const float*)d_in[0];   // [16,1280,768] f32
    const float* emb    = (const float*)d_in[1];   // [50000,768] f32
    const int*   pos    = (const int*)  d_in[3];   // [16,1280] i32
    float* out = (float*)d_out;                    // [16,50000] f32

    cudaFuncSetAttribute(gemm_mma, cudaFuncAttributeMaxDynamicSharedMemorySize, DSMEM_BYTES);

    prep_kernel<<<PREP_GRID, 256>>>(hidden, pos, emb);
    gemm_mma<<<dim3(MP / BM, NP / BN), 256, DSMEM_BYTES>>>();
    finalize_kernel<<<(B_ * NI + 255) / 256, 256>>>(out);
}

// round 13
// speedup vs baseline: 2.6963x; 1.3231x over previous
#include <cuda_runtime.h>
#include <cuda_fp16.h>
#include <math_constants.h>
#include <cstdint>

// ---------------- Problem constants ----------------
#define B_    16
#define S_    20
#define RPB   24               // rows per batch session group (pad 20 -> 24)
#define T_    1280
#define H_    768
#define NI    50000
#define NP    50176            // N padded to multiple of 256
#define MP    (B_ * RPB)       // 384 padded M rows
#define TEMP_ 0.05f
#define EPS_  1e-8f

// ---------------- GEMM config ----------------
#define BM 128
#define BN 256
#define BK 64
#define NSTAGE 3
#define NKCH (H_ / BK)          // 12
#define ATILE_B  16384          // 128 rows x 128B
#define ETILE_B  32768          // 256 rows x 128B
#define STAGE_B  (ATILE_B + ETILE_B)            // 48KB
#define DSMEM_BYTES (NSTAGE * STAGE_B + 1024)   // 148480
#define GT 512

#define NEG_ORD 0x007FFFFFu     // f2o(-inf)

// ---------------- Scratch (device globals) ----------------
__device__ __half   g_Ahf[(size_t)MP * H_];    // pooled, normalized, /TEMP
__device__ __half   g_Ehf[(size_t)NP * H_];    // prescaled by 1/||e||
__device__ float    g_valid[MP];
__device__ unsigned g_outU[(size_t)B_ * NP];   // ordered-uint maxsim accumulator

// ---------------- helpers ----------------
static __device__ __forceinline__ uint32_t smem_u32(const void* p) {
    uint32_t a;
    asm("{ .reg .u64 t; cvta.to.shared.u64 t, %1; cvt.u32.u64 %0, t; }" : "=r"(a) : "l"(p));
    return a;
}
static __device__ __forceinline__ uint32_t sw128(uint32_t o) { return o ^ ((o >> 3) & 0x70); }

static __device__ __forceinline__ void cp16(uint32_t dst, const void* src) {
    asm volatile("cp.async.cg.shared.global [%0], [%1], 16;" :: "r"(dst), "l"(src));
}
#define CP_COMMIT()   asm volatile("cp.async.commit_group;" ::: "memory")
#define CP_WAIT(n)    asm volatile("cp.async.wait_group %0;" :: "n"(n) : "memory")

static __device__ __forceinline__ void ldsm_x4(uint32_t* r, uint32_t addr) {
    asm volatile("ldmatrix.sync.aligned.m8n8.x4.shared.b16 {%0,%1,%2,%3}, [%4];"
        : "=r"(r[0]), "=r"(r[1]), "=r"(r[2]), "=r"(r[3]) : "r"(addr));
}
static __device__ __forceinline__ void mma16816(float* d, const uint32_t* a, const uint32_t* b) {
    asm volatile("mma.sync.aligned.m16n8k16.row.col.f32.f16.f16.f32 "
        "{%0,%1,%2,%3}, {%4,%5,%6,%7}, {%8,%9}, {%0,%1,%2,%3};"
        : "+f"(d[0]), "+f"(d[1]), "+f"(d[2]), "+f"(d[3])
        : "r"(a[0]), "r"(a[1]), "r"(a[2]), "r"(a[3]), "r"(b[0]), "r"(b[1]));
}
static __device__ __forceinline__ unsigned f2o(float x) {
    unsigned u = __float_as_uint(x);
    return (u >> 31) ? ~u : (u | 0x80000000u);
}
static __device__ __forceinline__ float o2f(unsigned u) {
    return (u >> 31) ? __uint_as_float(u & 0x7fffffffu) : __uint_as_float(~u);
}

// ---------------------------------------------------------------------------
// Kernel 1 (fused prep): three block roles.
//   blocks [0, MP)            : pooling -> fp16 A + validity
//   blocks [MP, MP + NP/8)    : E fp32 -> normalize -> fp16 (8 rows/blk)
//   blocks [MP+NP/8, ...)     : init g_outU to NEG_ORD
// ---------------------------------------------------------------------------
#define EPREP_BLKS (NP / 8)                  // 6272
#define INIT_BLKS  ((B_ * NP + 2047) / 2048) // 392
#define PREP_GRID  (MP + EPREP_BLKS + INIT_BLKS)

__global__ __launch_bounds__(256)
void prep_kernel(const float* __restrict__ hidden,
                 const int*   __restrict__ pos,
                 const float* __restrict__ emb) {
    const int blk = blockIdx.x;
    const int tid = threadIdx.x;

    // ---------------- role 3: output-accumulator init ----------------
    if (blk >= MP + EPREP_BLKS) {
        const int rb = blk - MP - EPREP_BLKS;
        #pragma unroll
        for (int k = 0; k < 8; k++) {
            int idx = rb * 2048 + k * 256 + tid;
            if (idx < B_ * NP) g_outU[idx] = NEG_ORD;
        }
        return;
    }

    // ---------------- role 2: E prep ----------------
    if (blk >= MP) {
        const int n = (blk - MP) * 8 + (tid >> 5);
        const int lane = tid & 31;
        uint2* hrow = (uint2*)&g_Ehf[(size_t)n * H_];   // 8B = 4 halves
        if (n >= NI) {
            #pragma unroll
            for (int u = 0; u < 6; u++)
                hrow[u * 32 + lane] = make_uint2(0u, 0u);
            return;
        }
        const float4* erow = (const float4*)&emb[(size_t)n * H_];
        float4 x[6];
        float ssq = 0.f;
        #pragma unroll
        for (int u = 0; u < 6; u++) {
            x[u] = erow[u * 32 + lane];
            ssq += x[u].x * x[u].x + x[u].y * x[u].y + x[u].z * x[u].z + x[u].w * x[u].w;
        }
        #pragma unroll
        for (int o = 16; o; o >>= 1) ssq += __shfl_xor_sync(0xffffffffu, ssq, o);
        const float invn = 1.f / fmaxf(sqrtf(ssq), EPS_);
        #pragma unroll
        for (int u = 0; u < 6; u++) {
            __half2 p0 = __floats2half2_rn(x[u].x * invn, x[u].y * invn);
            __half2 p1 = __floats2half2_rn(x[u].z * invn, x[u].w * invn);
            hrow[u * 32 + lane] = make_uint2(*(uint32_t*)&p0, *(uint32_t*)&p1);
        }
        return;
    }

    // ---------------- role 1: pooling ----------------
    const int b = blk / RPB, s = blk % RPB;
    uint32_t* ahr = (uint32_t*)&g_Ahf[(size_t)blk * H_];   // 384 uint32

    __shared__ int   spos[64];
    __shared__ float red[8];

    int cnt = 0;
    if (s < S_) {
        if (tid < 64) spos[tid] = pos[b * T_ + s * 64 + tid];
        __syncthreads();
        const int target = s + 1;
        #pragma unroll 8
        for (int t = 0; t < 64; t++) cnt += (spos[t] == target);
    }

    if (cnt == 0) {
        #pragma unroll
        for (int k = 0; k < 2; k++) {
            int i = tid + k * 256;
            if (i < H_ / 2) ahr[i] = 0u;
        }
        if (tid == 0) g_valid[blk] = 0.f;
        return;
    }

    const int target = s + 1;
    const float* hb = hidden + ((size_t)b * T_ + (size_t)s * 64) * H_;
    float a0 = 0.f, a1 = 0.f, a2 = 0.f;
    #pragma unroll 8
    for (int t = 0; t < 64; t++) {
        float m = (spos[t] == target) ? 1.f : 0.f;
        const float* r = hb + (size_t)t * H_;
        a0 += m * r[tid];
        a1 += m * r[tid + 256];
        a2 += m * r[tid + 512];
    }
    const float inv_c = 1.f / (float)cnt;
    a0 *= inv_c; a1 *= inv_c; a2 *= inv_c;

    float ss = a0 * a0 + a1 * a1 + a2 * a2;
    #pragma unroll
    for (int o = 16; o; o >>= 1) ss += __shfl_down_sync(0xffffffffu, ss, o);
    if ((tid & 31) == 0) red[tid >> 5] = ss;
    __syncthreads();
    if (tid < 8) {
        float v = red[tid];
        #pragma unroll
        for (int o = 4; o; o >>= 1) v += __shfl_down_sync(0xffu, v, o);
        if (tid == 0) red[0] = v;
    }
    __syncthreads();

    const float scale = 1.f / (fmaxf(sqrtf(red[0]), EPS_) * TEMP_);
    g_Ahf[(size_t)blk * H_ + tid]       = __float2half_rn(a0 * scale);
    g_Ahf[(size_t)blk * H_ + tid + 256] = __float2half_rn(a1 * scale);
    g_Ahf[(size_t)blk * H_ + tid + 512] = __float2half_rn(a2 * scale);
    if (tid == 0) g_valid[blk] = 1.f;
}

// ---------------------------------------------------------------------------
// Kernel 2: fp16 mma.sync GEMM + maxsim epilogue.
// grid = (MP/128 = 3, NP/256 = 196), 512 threads = 16 warps (2m x 8n,
// warp tile m64n32), 3-stage cp.async pipeline, 1 CTA/SM (4 warps/SMSP).
// ---------------------------------------------------------------------------
__global__ __launch_bounds__(GT, 1)
void gemm_mma() {
    extern __shared__ __align__(16) char dsm[];
    __shared__ unsigned s_red[6][BN];
    __shared__ float s_val[BM];

    const int tid  = threadIdx.x;
    const int wid  = tid >> 5;
    const int lane = tid & 31;
    const int wm   = wid >> 3;        // 0..1  (m64 tile)
    const int wn   = wid & 7;         // 0..7  (n32 tile)
    const int m0   = blockIdx.x * BM;
    const int n0   = blockIdx.y * BN;
    const int gbase = m0 / RPB;       // 0, 5, 10

    const uint32_t base = (smem_u32(dsm) + 1023u) & ~1023u;

    if (tid < BM) s_val[tid] = g_valid[m0 + tid];
    #pragma unroll
    for (int k = 0; k < 3; k++) {
        int i = tid + k * GT;
        if (i < 6 * BN) s_red[i >> 8][i & 255] = NEG_ORD;
    }

    auto issue_loads = [&](int kc, int stg) {
        const uint32_t sb = base + stg * STAGE_B;
        // A tile: 128 rows x 128B = 1024 chunks (2 per thread)
        {
            const __half* src = g_Ahf + (size_t)m0 * H_;
            #pragma unroll
            for (int j = 0; j < 2; j++) {
                int i = tid + j * GT;         // 0..1023
                int row = i >> 3, u = i & 7;
                cp16(sb + sw128((uint32_t)(row * 128 + u * 16)),
                     src + (size_t)row * H_ + kc * BK + u * 8);
            }
        }
        // E tile: 256 rows x 128B = 2048 chunks (4 per thread)
        {
            const __half* src = g_Ehf + (size_t)n0 * H_;
            #pragma unroll
            for (int j = 0; j < 4; j++) {
                int i = tid + j * GT;         // 0..2047
                int row = i >> 3, u = i & 7;
                cp16(sb + ATILE_B + sw128((uint32_t)(row * 128 + u * 16)),
                     src + (size_t)row * H_ + kc * BK + u * 8);
            }
        }
        CP_COMMIT();
    };

    float acc[4][4][4];
    #pragma unroll
    for (int mi = 0; mi < 4; mi++)
        #pragma unroll
        for (int ni = 0; ni < 4; ni++)
            #pragma unroll
            for (int q = 0; q < 4; q++) acc[mi][ni][q] = 0.f;

    // per-lane ldmatrix row offsets (bytes), within a tile
    const uint32_t a_row = (uint32_t)(wm * 64 + ((lane >> 3) & 1) * 8 + (lane & 7)) * 128;
    const uint32_t a_u   = (uint32_t)((lane >> 4) & 1) * 16;
    const uint32_t b_row = (uint32_t)(wn * 32 + ((lane >> 4) & 1) * 8 + (lane & 7)) * 128;
    const uint32_t b_u   = (uint32_t)((lane >> 3) & 1) * 16;

    issue_loads(0, 0);
    issue_loads(1, 1);

    for (int kc = 0; kc < NKCH; kc++) {
        CP_WAIT(1);
        __syncthreads();
        if (kc + 2 < NKCH) issue_loads(kc + 2, (kc + 2) % NSTAGE);

        const uint32_t sb = base + (kc % NSTAGE) * STAGE_B;
        const uint32_t As = sb;
        const uint32_t Es = sb + ATILE_B;

        #pragma unroll
        for (int s = 0; s < 4; s++) {
            const uint32_t ku = (uint32_t)(s * 32);
            uint32_t ah[4][4], bh[2][4];
            #pragma unroll
            for (int mi = 0; mi < 4; mi++)
                ldsm_x4(ah[mi], As + sw128(a_row + (uint32_t)(mi * 16 * 128) + ku + a_u));
            #pragma unroll
            for (int nj = 0; nj < 2; nj++)
                ldsm_x4(bh[nj], Es + sw128(b_row + (uint32_t)(nj * 16 * 128) + ku + b_u));
            #pragma unroll
            for (int mi = 0; mi < 4; mi++)
                #pragma unroll
                for (int ni = 0; ni < 4; ni++)
                    mma16816(acc[mi][ni], ah[mi], &bh[ni >> 1][(ni & 1) * 2]);
        }
    }

    // ---- epilogue: mask, per-session max via smem ordered atomicMax ----
    #pragma unroll
    for (int mi = 0; mi < 4; mi++) {
        const int r0 = wm * 64 + mi * 16 + (lane >> 2);
        const int r1 = r0 + 8;
        const bool ok0 = s_val[r0] > 0.5f;
        const bool ok1 = s_val[r1] > 0.5f;
        const int lg0 = (m0 + r0) / RPB - gbase;
        const int lg1 = (m0 + r1) / RPB - gbase;
        #pragma unroll
        for (int ni = 0; ni < 4; ni++) {
            const int c = wn * 32 + ni * 8 + (lane & 3) * 2;
            unsigned u0 = ok0 ? f2o(acc[mi][ni][0]) : NEG_ORD;
            unsigned u1 = ok0 ? f2o(acc[mi][ni][1]) : NEG_ORD;
            unsigned u2 = ok1 ? f2o(acc[mi][ni][2]) : NEG_ORD;
            unsigned u3 = ok1 ? f2o(acc[mi][ni][3]) : NEG_ORD;
            if (lg0 == lg1) {
                atomicMax(&s_red[lg0][c],     u0 > u2 ? u0 : u2);
                atomicMax(&s_red[lg0][c + 1], u1 > u3 ? u1 : u3);
            } else {
                atomicMax(&s_red[lg0][c],     u0);
                atomicMax(&s_red[lg0][c + 1], u1);
                atomicMax(&s_red[lg1][c],     u2);
                atomicMax(&s_red[lg1][c + 1], u3);
            }
        }
    }
    __syncthreads();

    // combine into global ordered-uint accumulator (groups may straddle tiles)
    #pragma unroll
    for (int k = 0; k < 3; k++) {
        int i = tid + k * GT;
        if (i < 6 * BN) {
            int lg = i >> 8, c = i & 255;
            int g = gbase + lg;
            unsigned v = s_red[lg][c];
            if (g < B_ && v != NEG_ORD)
                atomicMax(&g_outU[(size_t)g * NP + n0 + c], v);
        }
    }
}

// ---------------------------------------------------------------------------
// Kernel 3: finalize -> decode ordered-uint to float output.
// ---------------------------------------------------------------------------
__global__ __launch_bounds__(256)
void finalize_kernel(float* __restrict__ out) {
    int i = blockIdx.x * 256 + threadIdx.x;
    if (i < B_ * NI) {
        int b = i / NI, n = i - b * NI;
        out[i] = o2f(g_outU[(size_t)b * NP + n]);
    }
}

// ---------------------------------------------------------------------------
// Launch
// ---------------------------------------------------------------------------
extern "C" void kernel_launch(void* const* d_in, const int* in_sizes, int n_in,
                              void* d_out, int out_size) {
    const float* hidden = (const float*)d_in[0];   // [16,1280,768] f32
    const float* emb    = (const float*)d_in[1];   // [50000,768] f32
    const int*   pos    = (const int*)  d_in[3];   // [16,1280] i32
    float* out = (float*)d_out;                    // [16,50000] f32

    cudaFuncSetAttribute(gemm_mma, cudaFuncAttributeMaxDynamicSharedMemorySize, DSMEM_BYTES);

    prep_kernel<<<PREP_GRID, 256>>>(hidden, pos, emb);
    gemm_mma<<<dim3(MP / BM, NP / BN), GT, DSMEM_BYTES>>>();
    finalize_kernel<<<(B_ * NI + 255) / 256, 256>>>(out);
}